// round 14
// baseline (speedup 1.0000x reference)
#include <cuda_runtime.h>
#include <math.h>

// feat: [B=4, C=256, H=50, W=50] f32;  rois: [R,5] f32;  out: [R,256,7,7] f32
#define BB 4
#define CC 256
#define HW 2500
#define HH 50
#define WW 50
#define PP 7
#define NBIN 49
#define SPATIAL_SCALE 0.0625f

// Channel-last features: featT[b][cell][c] — a bin-cell gather becomes a
// contiguous 256-float vector read (perfectly coalesced across lanes).
__device__ __align__(16) float g_featT[BB * HW * CC];

// ---------------- transpose: [b][c][s] -> [b][s][c] ----------------
// Block: 128 c x 32 s tile. Read coalesced over s; write float4 over c.
__global__ void __launch_bounds__(256)
transpose_kernel(const float* __restrict__ feat) {
    __shared__ float tile[128][33];
    const int s0 = blockIdx.x * 32;
    const int c0 = blockIdx.y * 128;
    const int b  = blockIdx.z;
    const int t    = threadIdx.x;
    const int lane = t & 31;
    const int w    = t >> 5;

    const int s_rd = s0 + lane;
    if (s_rd < HW) {
        const float* fp = feat + ((size_t)b * CC + c0 + w) * HW + s_rd;
        #pragma unroll
        for (int k = 0; k < 16; ++k)
            tile[w + 8 * k][lane] = __ldg(fp + (size_t)(8 * k) * HW);
    }
    __syncthreads();

    const int sw = t >> 3;              // 0..31
    const int cq = (t & 7) * 16;        // 16 channels per thread
    const int s_wr = s0 + sw;
    if (s_wr < HW) {
        float4* dst = (float4*)(g_featT + ((size_t)b * HW + s_wr) * CC + c0 + cq);
        #pragma unroll
        for (int m = 0; m < 4; ++m) {
            float4 v;
            v.x = tile[cq + 4 * m + 0][sw];
            v.y = tile[cq + 4 * m + 1][sw];
            v.z = tile[cq + 4 * m + 2][sw];
            v.w = tile[cq + 4 * m + 3][sw];
            dst[m] = v;
        }
    }
}

// ---------------- gather: warp = one bin, lane = 4 channels ----------------
// Block = (pg, cg, r): 8 bins (p = pg*8+w) x 128 channels (c0 = cg*128).
__global__ void __launch_bounds__(256)
roipool_kernel(const float* __restrict__ rois, float* __restrict__ out) {
    __shared__ int      s_off[8];        // hs*50 + ws (cell offset)
    __shared__ unsigned s_msk[8];        // 16-bit 4x4 validity mask
    __shared__ int      s_cb;            // b * 2500
    __shared__ __align__(16) float s_out[8][132];   // stride 132: 4w+c banks distinct

    const int pg = blockIdx.x;           // 0..6
    const int c0 = blockIdx.y << 7;      // 0 or 128
    const int r  = blockIdx.z;
    const int t    = threadIdx.x;
    const int lane = t & 31;
    const int w    = t >> 5;

    if (t < 8) {
        const int p = pg * 8 + t;
        unsigned mask = 0;
        int off = 0;
        if (p < NBIN) {
            const float* rp = rois + (size_t)r * 5;
            // jnp.round == round-half-to-even == rintf (RN); *0.0625 exact.
            float x1 = rintf(rp[1] * SPATIAL_SCALE);
            float y1 = rintf(rp[2] * SPATIAL_SCALE);
            float x2 = rintf(rp[3] * SPATIAL_SCALE);
            float y2 = rintf(rp[4] * SPATIAL_SCALE);
            // XLA folds x/7 into x * RN(1/7); replicate exactly.
            const float INV7 = 1.0f / 7.0f;
            float bw = __fmul_rn(fmaxf(x2 - x1 + 1.0f, 1.0f), INV7);
            float bh = __fmul_rn(fmaxf(y2 - y1 + 1.0f, 1.0f), INV7);
            float fpw = (float)(p % PP);
            float fph = (float)(p / PP);
            int ws = (int)fminf(fmaxf(floorf(__fmul_rn(bw, fpw))        + x1, 0.0f), (float)WW);
            int we = (int)fminf(fmaxf(ceilf (__fmul_rn(bw, fpw + 1.0f)) + x1, 0.0f), (float)WW);
            int hs = (int)fminf(fmaxf(floorf(__fmul_rn(bh, fph))        + y1, 0.0f), (float)HH);
            int he = (int)fminf(fmaxf(ceilf (__fmul_rn(bh, fph + 1.0f)) + y1, 0.0f), (float)HH);
            int nw = we - ws;            // 0..4 (window provably <= 4x4)
            int nh = he - hs;
            unsigned rowpat = (nw > 0) ? ((1u << nw) - 1u) : 0u;
            unsigned rows   = (nh > 0) ? (0x1111u & ((1u << (4 * nh)) - 1u)) : 0u;
            mask = rowpat * rows;        // bit (i*4+j)
            off  = hs * WW + ws;
        }
        s_msk[t] = mask;
        s_off[t] = off;
        if (t == 0) s_cb = (int)rois[(size_t)r * 5] * HW;
    }
    __syncthreads();

    // Gather: warp-uniform mask; each taken slot = one coalesced LDG.128.
    {
        const unsigned mask = s_msk[w];
        const float4* base = (const float4*)(g_featT
            + ((size_t)(s_cb + s_off[w])) * CC + c0) + lane;

        float m0 = -INFINITY, m1 = -INFINITY, m2 = -INFINITY, m3 = -INFINITY;
        #pragma unroll
        for (int i = 0; i < 4; ++i) {
            #pragma unroll
            for (int j = 0; j < 4; ++j) {
                if (mask & (1u << (i * 4 + j))) {
                    float4 v = __ldg(base + (i * WW + j) * (CC / 4));
                    m0 = fmaxf(m0, v.x);
                    m1 = fmaxf(m1, v.y);
                    m2 = fmaxf(m2, v.z);
                    m3 = fmaxf(m3, v.w);
                }
            }
        }
        float4 o;
        o.x = (m0 == -INFINITY) ? 0.0f : m0;
        o.y = (m1 == -INFINITY) ? 0.0f : m1;
        o.z = (m2 == -INFINITY) ? 0.0f : m2;
        o.w = (m3 == -INFINITY) ? 0.0f : m3;
        ((float4*)&s_out[w][0])[lane] = o;
    }
    __syncthreads();

    // Writeback: out[(r*256 + c0+c)*49 + p], p = pg*8 + w.
    #pragma unroll
    for (int k = 0; k < 4; ++k) {
        int o = t + 256 * k;             // 0..1023
        int c = o >> 3;                  // 0..127
        int ww = o & 7;
        int p  = pg * 8 + ww;
        if (p < NBIN)
            out[((size_t)(r * CC + c0 + c)) * NBIN + p] = s_out[ww][c];
    }
}

extern "C" void kernel_launch(void* const* d_in, const int* in_sizes, int n_in,
                              void* d_out, int out_size) {
    const float* feat = (const float*)d_in[0];
    const float* rois = (const float*)d_in[1];
    float* out = (float*)d_out;

    int R = in_sizes[1] / 5;                     // 128

    dim3 tgrid((HW + 31) / 32, CC / 128, BB);    // 79 x 2 x 4 = 632
    transpose_kernel<<<tgrid, 256>>>(feat);

    dim3 ggrid(7, CC / 128, R);                  // 7 x 2 x 128 = 1792
    roipool_kernel<<<ggrid, 256>>>(rois, out);
}

// round 15
// speedup vs baseline: 1.1533x; 1.1533x over previous
#include <cuda_runtime.h>
#include <math.h>

// feat: [B=4, C=256, H=50, W=50] f32;  rois: [R,5] f32;  out: [R,256,7,7] f32
#define BB 4
#define CC 256
#define HW 2500
#define HH 50
#define WW 50
#define PP 7
#define NBIN 49
#define SPATIAL_SCALE 0.0625f

// Channel-last features: featT[b][cell][c].
__device__ __align__(16) float g_featT[BB * HW * CC];

// ---------------- transpose: [b][c][s] -> [b][s][c], float4 both sides ----
__global__ void __launch_bounds__(256)
transpose_kernel(const float* __restrict__ feat) {
    __shared__ float tile[64][65];
    const int s0 = blockIdx.x * 64;
    const int c0 = blockIdx.y * 64;
    const int b  = blockIdx.z;
    const int t  = threadIdx.x;

    // Read: thread (cr, sq) loads 4 float4s of row c0+cr (row base is 16B-aligned:
    // c*2500*4B = c*10000, and 10000 % 16 == 0).
    {
        const int cr = t >> 2, sq = t & 3;
        const float* src = feat + ((size_t)(b * CC + c0 + cr)) * HW + s0;
        #pragma unroll
        for (int k = 0; k < 4; ++k) {
            int sf = 4 * (sq + 4 * k);          // 0..60
            if (s0 + sf + 3 < HW) {
                float4 v = *(const float4*)(src + sf);
                tile[cr][sf + 0] = v.x; tile[cr][sf + 1] = v.y;
                tile[cr][sf + 2] = v.z; tile[cr][sf + 3] = v.w;
            } else {
                #pragma unroll
                for (int e = 0; e < 4; ++e)
                    if (s0 + sf + e < HW) tile[cr][sf + e] = src[sf + e];
            }
        }
    }
    __syncthreads();

    // Write: thread (sr, cq) stores 4 float4s over c for cell s0+sr.
    {
        const int sr = t >> 2, cq = t & 3;
        if (s0 + sr < HW) {
            float* dst = g_featT + ((size_t)(b * HW + s0 + sr)) * CC + c0;
            #pragma unroll
            for (int k = 0; k < 4; ++k) {
                int cf = 4 * (cq + 4 * k);
                float4 v;
                v.x = tile[cf + 0][sr]; v.y = tile[cf + 1][sr];
                v.z = tile[cf + 2][sr]; v.w = tile[cf + 3][sr];
                *(float4*)(dst + cf) = v;
            }
        }
    }
}

// ---------------- gather: warp = one bin, lane = 4 channels ----------------
// Block = (pg, cg, r): 7 warps = bins p = pg*7+w; 128 channels c0 = cg*128.
// Each warp decodes its own bin in registers: no cross-warp decode dependency.
__global__ void __launch_bounds__(224)
roipool_kernel(const float* __restrict__ rois, float* __restrict__ out) {
    __shared__ __align__(16) float s_out[PP][132];

    const int pg = blockIdx.x;           // 0..6
    const int c0 = blockIdx.y << 7;      // 0 or 128
    const int r  = blockIdx.z;
    const int t    = threadIdx.x;
    const int lane = t & 31;
    const int w    = t >> 5;             // 0..6
    const int p    = pg * PP + w;        // 0..48 exactly

    const float* rp = rois + (size_t)r * 5;
    // jnp.round == round-half-to-even == rintf (RN); *0.0625 exact.
    float x1 = rintf(rp[1] * SPATIAL_SCALE);
    float y1 = rintf(rp[2] * SPATIAL_SCALE);
    float x2 = rintf(rp[3] * SPATIAL_SCALE);
    float y2 = rintf(rp[4] * SPATIAL_SCALE);
    // XLA folds x/7 into x * RN(1/7); replicate exactly.
    const float INV7 = 1.0f / 7.0f;
    float bw = __fmul_rn(fmaxf(x2 - x1 + 1.0f, 1.0f), INV7);
    float bh = __fmul_rn(fmaxf(y2 - y1 + 1.0f, 1.0f), INV7);
    float fpw = (float)(p % PP);
    float fph = (float)(p / PP);
    int ws = (int)fminf(fmaxf(floorf(__fmul_rn(bw, fpw))        + x1, 0.0f), (float)WW);
    int we = (int)fminf(fmaxf(ceilf (__fmul_rn(bw, fpw + 1.0f)) + x1, 0.0f), (float)WW);
    int hs = (int)fminf(fmaxf(floorf(__fmul_rn(bh, fph))        + y1, 0.0f), (float)HH);
    int he = (int)fminf(fmaxf(ceilf (__fmul_rn(bh, fph + 1.0f)) + y1, 0.0f), (float)HH);
    int nw = we - ws;                    // 0..4 (window provably <= 4x4)
    int nh = he - hs;
    unsigned rowpat = (nw > 0) ? ((1u << nw) - 1u) : 0u;
    unsigned rows   = (nh > 0) ? (0x1111u & ((1u << (4 * nh)) - 1u)) : 0u;
    const unsigned mask = rowpat * rows; // bit (i*4+j), warp-uniform
    const int cb = (int)rp[0] * HW;

    const float4* base = (const float4*)(g_featT
        + ((size_t)(cb + hs * WW + ws)) * CC + c0) + lane;

    // Warp-uniform mask; each taken slot = one coalesced 512B LDG.128 wavefront.
    float m0 = -INFINITY, m1 = -INFINITY, m2 = -INFINITY, m3 = -INFINITY;
    #pragma unroll
    for (int i = 0; i < 4; ++i) {
        #pragma unroll
        for (int j = 0; j < 4; ++j) {
            if (mask & (1u << (i * 4 + j))) {
                float4 v = __ldg(base + (i * WW + j) * (CC / 4));
                m0 = fmaxf(m0, v.x);
                m1 = fmaxf(m1, v.y);
                m2 = fmaxf(m2, v.z);
                m3 = fmaxf(m3, v.w);
            }
        }
    }
    float4 o;
    o.x = (m0 == -INFINITY) ? 0.0f : m0;
    o.y = (m1 == -INFINITY) ? 0.0f : m1;
    o.z = (m2 == -INFINITY) ? 0.0f : m2;
    o.w = (m3 == -INFINITY) ? 0.0f : m3;
    ((float4*)&s_out[w][0])[lane] = o;
    __syncthreads();

    // Writeback: 896 outputs = 128 c x 7 ww; out[(r*256+c0+c)*49 + pg*7 + ww].
    #pragma unroll
    for (int k = 0; k < 4; ++k) {
        int oidx = t + 224 * k;          // 0..895
        int c  = oidx / PP;
        int ww = oidx - c * PP;
        out[((size_t)(r * CC + c0 + c)) * NBIN + pg * PP + ww] = s_out[ww][c];
    }
}

extern "C" void kernel_launch(void* const* d_in, const int* in_sizes, int n_in,
                              void* d_out, int out_size) {
    const float* feat = (const float*)d_in[0];
    const float* rois = (const float*)d_in[1];
    float* out = (float*)d_out;

    int R = in_sizes[1] / 5;                     // 128

    dim3 tgrid((HW + 63) / 64, CC / 64, BB);     // 40 x 4 x 4 = 640
    transpose_kernel<<<tgrid, 256>>>(feat);

    dim3 ggrid(PP, CC / 128, R);                 // 7 x 2 x 128 = 1792
    roipool_kernel<<<ggrid, 224>>>(rois, out);
}